// round 2
// baseline (speedup 1.0000x reference)
#include <cuda_runtime.h>

// cumulative_hazard: per-row tiny RNN (11 steps, 8 neurons, 9 inputs) + 3 dense layers.
// Strategy: 2 rows packed per thread via fp32x2 packed FMA (sm_100+), weights
// preprocessed (softplus folded) into shared as duplicated pairs.

typedef unsigned long long u64;

#define NTHREADS 256

__device__ __forceinline__ u64 pack2(float lo, float hi) {
    u64 d; asm("mov.b64 %0, {%1, %2};" : "=l"(d) : "f"(lo), "f"(hi)); return d;
}
__device__ __forceinline__ void unpack2(u64 v, float& lo, float& hi) {
    asm("mov.b64 {%0, %1}, %2;" : "=f"(lo), "=f"(hi) : "l"(v));
}
__device__ __forceinline__ u64 ffma2(u64 a, u64 b, u64 c) {
    u64 d; asm("fma.rn.f32x2 %0, %1, %2, %3;" : "=l"(d) : "l"(a), "l"(b), "l"(c)); return d;
}

// accurate tanh: 2 MUFU (EX2 + RCP), ~1e-6 error
__device__ __forceinline__ float tanh_acc(float x) {
    float e = __expf(-2.0f * x);          // FMUL + MUFU.EX2
    return 1.0f - __fdividef(e + e, 1.0f + e);  // FADD,FADD,MUFU.RCP,FMUL,FADD
}
__device__ __forceinline__ u64 tanh2(u64 v) {
    float a, b; unpack2(v, a, b);
    return pack2(tanh_acc(a), tanh_acc(b));
}

// numerically stable softplus (only 2 per thread; use precise path)
__device__ __forceinline__ float softplus_out(float x) {
    float ax = fabsf(x);
    float l = log1pf(__expf(-ax));
    return x > 0.0f ? x + l : l;
}
__device__ __forceinline__ float sp_precise(float x) {  // for weight preprocessing
    float ax = fabsf(x);
    float l = log1pf(expf(-ax));
    return x > 0.0f ? x + l : l;
}

__global__ __launch_bounds__(NTHREADS, 1)
void hazard_kernel(const float* __restrict__ Y,     // [N,16]
                   const float* __restrict__ tau,   // [N,1]
                   const float* __restrict__ f1W,   // [8,9]
                   const float* __restrict__ f1b,   // [8]
                   const float* __restrict__ ftW,   // [8,1]
                   const float* __restrict__ ftb,   // [8]
                   const float* __restrict__ f20W,  // [8,8]
                   const float* __restrict__ f20b,  // [8]
                   const float* __restrict__ f21W,  // [8,8]
                   const float* __restrict__ f21b,  // [8]
                   const float* __restrict__ f22W,  // [1,8]
                   const float* __restrict__ f22b,  // [1]
                   float* __restrict__ out,         // [N]
                   int npairs)
{
    __shared__ u64 sW1[72], sB1[8];
    __shared__ u64 sW20[64], sB20[8], sTW[8];
    __shared__ u64 sW21[64], sB21[8];
    __shared__ u64 sW22[8], sB22;

    const int t = threadIdx.x;
    // ---- per-block weight preprocessing (softplus folded, duplicated pairs) ----
    if (t < 72)        { float v = f1W[t];                         sW1[t] = pack2(v, v); }
    else if (t < 80)   { int i = t - 72;  float v = f1b[i];        sB1[i] = pack2(v, v); }
    else if (t < 144)  { int i = t - 80;  float v = f20W[i];       sW20[i] = pack2(v, v); }
    else if (t < 152)  { int i = t - 144; float v = f20b[i] + sp_precise(ftb[i]); sB20[i] = pack2(v, v); }
    else if (t < 160)  { int i = t - 152; float v = sp_precise(ftW[i]);  sTW[i] = pack2(v, v); }
    else if (t < 224)  { int i = t - 160; float v = sp_precise(f21W[i]); sW21[i] = pack2(v, v); }
    else if (t < 232)  { int i = t - 224; float v = sp_precise(f21b[i]); sB21[i] = pack2(v, v); }
    else if (t < 240)  { int i = t - 232; float v = sp_precise(f22W[i]); sW22[i] = pack2(v, v); }
    else if (t == 240) { float v = sp_precise(f22b[0]);            sB22 = pack2(v, v); }
    __syncthreads();

    const int gid = blockIdx.x * NTHREADS + t;
    if (gid >= npairs) return;

    const long long r0 = (long long)gid * 2;

    // ---- load 2 rows of Y_seq (32 floats, 128B contiguous per thread) ----
    const float4* yp = (const float4*)(Y + r0 * 16);
    float4 q0 = yp[0], q1 = yp[1], q2 = yp[2], q3 = yp[3];  // row r0
    float4 p0 = yp[4], p1 = yp[5], p2 = yp[6], p3 = yp[7];  // row r0+1

    float ra[16] = { q0.x,q0.y,q0.z,q0.w, q1.x,q1.y,q1.z,q1.w,
                     q2.x,q2.y,q2.z,q2.w, q3.x,q3.y,q3.z,q3.w };
    float rb[16] = { p0.x,p0.y,p0.z,p0.w, p1.x,p1.y,p1.z,p1.w,
                     p2.x,p2.y,p2.z,p2.w, p3.x,p3.y,p3.z,p3.w };

    // y[j] = log(Y[:,4+j] - Y[:,3+j] + 0.1), j = 0..10 (scan uses first 11 diffs)
    u64 y[11];
#pragma unroll
    for (int j = 0; j < 11; j++) {
        float d0 = __logf(ra[4 + j] - ra[3 + j] + 0.1f);
        float d1 = __logf(rb[4 + j] - rb[3 + j] + 0.1f);
        y[j] = pack2(d0, d1);
    }

    // ---- RNN: flow = tanh([flow, y_j] @ f1W^T + f1b), 11 steps ----
    u64 flow[8];
#pragma unroll
    for (int i = 0; i < 8; i++) flow[i] = 0ULL;  // pack2(0,0)

#pragma unroll
    for (int j = 0; j < 11; j++) {
        u64 acc[8];
#pragma unroll
        for (int i = 0; i < 8; i++) {
            u64 a1 = sB1[i];
#pragma unroll
            for (int k = 0; k < 8; k++) a1 = ffma2(flow[k], sW1[i * 9 + k], a1);
            a1 = ffma2(y[j], sW1[i * 9 + 8], a1);
            acc[i] = a1;
        }
#pragma unroll
        for (int i = 0; i < 8; i++) flow[i] = tanh2(acc[i]);
    }

    // ---- f2 layer 0: tanh(flow @ W20^T + b20' + tau * sp(Wtau)^T) ----
    u64 taup;
    {
        float2 tv = *(const float2*)(tau + r0);
        taup = pack2(tv.x, tv.y);
    }
    u64 g[8];
#pragma unroll
    for (int i = 0; i < 8; i++) {
        u64 a1 = sB20[i];
        a1 = ffma2(taup, sTW[i], a1);
#pragma unroll
        for (int k = 0; k < 8; k++) a1 = ffma2(flow[k], sW20[i * 8 + k], a1);
        g[i] = tanh2(a1);
    }

    // ---- f2 layer 1: tanh(g @ sp(W21)^T + sp(b21)) ----
    u64 h[8];
#pragma unroll
    for (int i = 0; i < 8; i++) {
        u64 a1 = sB21[i];
#pragma unroll
        for (int k = 0; k < 8; k++) a1 = ffma2(g[k], sW21[i * 8 + k], a1);
        h[i] = tanh2(a1);
    }

    // ---- output: softplus(h @ sp(W22)^T + sp(b22)) ----
    u64 o = sB22;
#pragma unroll
    for (int k = 0; k < 8; k++) o = ffma2(h[k], sW22[k], o);

    float o0, o1; unpack2(o, o0, o1);
    float2 res;
    res.x = softplus_out(o0);
    res.y = softplus_out(o1);
    *(float2*)(out + r0) = res;
}

extern "C" void kernel_launch(void* const* d_in, const int* in_sizes, int n_in,
                              void* d_out, int out_size)
{
    const float* Y    = (const float*)d_in[0];
    const float* tau  = (const float*)d_in[1];
    const float* f1W  = (const float*)d_in[2];
    const float* f1b  = (const float*)d_in[3];
    const float* ftW  = (const float*)d_in[4];
    const float* ftb  = (const float*)d_in[5];
    const float* f20W = (const float*)d_in[6];
    const float* f20b = (const float*)d_in[7];
    const float* f21W = (const float*)d_in[8];
    const float* f21b = (const float*)d_in[9];
    const float* f22W = (const float*)d_in[10];
    const float* f22b = (const float*)d_in[11];
    float* out = (float*)d_out;

    int npairs = out_size / 2;  // 2M threads, 2 rows each
    int blocks = (npairs + NTHREADS - 1) / NTHREADS;
    hazard_kernel<<<blocks, NTHREADS>>>(Y, tau, f1W, f1b, ftW, ftb,
                                        f20W, f20b, f21W, f21b, f22W, f22b,
                                        out, npairs);
}

// round 3
// speedup vs baseline: 1.8241x; 1.8241x over previous
#include <cuda_runtime.h>

// cumulative_hazard: per-row tiny RNN (11 steps, 8 neurons, 9 inputs) + 3 dense layers.
// R2: HW tanh (MUFU.TANH), step-0 specialization, 2 blocks/SM occupancy.
// 2 rows packed per thread via fp32x2 packed FMA; weights preprocessed
// (softplus folded) into shared as duplicated pairs.

typedef unsigned long long u64;

#define NTHREADS 256

__device__ __forceinline__ u64 pack2(float lo, float hi) {
    u64 d; asm("mov.b64 %0, {%1, %2};" : "=l"(d) : "f"(lo), "f"(hi)); return d;
}
__device__ __forceinline__ void unpack2(u64 v, float& lo, float& hi) {
    asm("mov.b64 {%0, %1}, %2;" : "=f"(lo), "=f"(hi) : "l"(v));
}
__device__ __forceinline__ u64 ffma2(u64 a, u64 b, u64 c) {
    u64 d; asm("fma.rn.f32x2 %0, %1, %2, %3;" : "=l"(d) : "l"(a), "l"(b), "l"(c)); return d;
}

// HW tanh: single MUFU.TANH per scalar (abs err ~2^-11; network amplification
// measured ~1x in R1, so final rel_err stays well under 1e-3)
__device__ __forceinline__ u64 tanh2(u64 v) {
    float a, b; unpack2(v, a, b);
    asm("tanh.approx.f32 %0, %0;" : "+f"(a));
    asm("tanh.approx.f32 %0, %0;" : "+f"(b));
    return pack2(a, b);
}

// numerically stable softplus (only 2 per thread; precise path)
__device__ __forceinline__ float softplus_out(float x) {
    float ax = fabsf(x);
    float l = log1pf(__expf(-ax));
    return x > 0.0f ? x + l : l;
}
__device__ __forceinline__ float sp_precise(float x) {  // weight preprocessing
    float ax = fabsf(x);
    float l = log1pf(expf(-ax));
    return x > 0.0f ? x + l : l;
}

__global__ __launch_bounds__(NTHREADS, 2)
void hazard_kernel(const float* __restrict__ Y,     // [N,16]
                   const float* __restrict__ tau,   // [N,1]
                   const float* __restrict__ f1W,   // [8,9]
                   const float* __restrict__ f1b,   // [8]
                   const float* __restrict__ ftW,   // [8,1]
                   const float* __restrict__ ftb,   // [8]
                   const float* __restrict__ f20W,  // [8,8]
                   const float* __restrict__ f20b,  // [8]
                   const float* __restrict__ f21W,  // [8,8]
                   const float* __restrict__ f21b,  // [8]
                   const float* __restrict__ f22W,  // [1,8]
                   const float* __restrict__ f22b,  // [1]
                   float* __restrict__ out,         // [N]
                   int npairs)
{
    __shared__ u64 sW1[72], sB1[8];
    __shared__ u64 sW20[64], sB20[8], sTW[8];
    __shared__ u64 sW21[64], sB21[8];
    __shared__ u64 sW22[8], sB22;

    const int t = threadIdx.x;
    // ---- per-block weight preprocessing (softplus folded, duplicated pairs) ----
    if (t < 72)        { float v = f1W[t];                         sW1[t] = pack2(v, v); }
    else if (t < 80)   { int i = t - 72;  float v = f1b[i];        sB1[i] = pack2(v, v); }
    else if (t < 144)  { int i = t - 80;  float v = f20W[i];       sW20[i] = pack2(v, v); }
    else if (t < 152)  { int i = t - 144; float v = f20b[i] + sp_precise(ftb[i]); sB20[i] = pack2(v, v); }
    else if (t < 160)  { int i = t - 152; float v = sp_precise(ftW[i]);  sTW[i] = pack2(v, v); }
    else if (t < 224)  { int i = t - 160; float v = sp_precise(f21W[i]); sW21[i] = pack2(v, v); }
    else if (t < 232)  { int i = t - 224; float v = sp_precise(f21b[i]); sB21[i] = pack2(v, v); }
    else if (t < 240)  { int i = t - 232; float v = sp_precise(f22W[i]); sW22[i] = pack2(v, v); }
    else if (t == 240) { float v = sp_precise(f22b[0]);            sB22 = pack2(v, v); }
    __syncthreads();

    const int gid = blockIdx.x * NTHREADS + t;
    if (gid >= npairs) return;

    const long long r0 = (long long)gid * 2;

    // ---- load 2 rows of Y_seq (32 floats, 128B contiguous per thread) ----
    const float4* yp = (const float4*)(Y + r0 * 16);
    float4 q0 = yp[0], q1 = yp[1], q2 = yp[2], q3 = yp[3];  // row r0
    float4 p0 = yp[4], p1 = yp[5], p2 = yp[6], p3 = yp[7];  // row r0+1

    float ra[16] = { q0.x,q0.y,q0.z,q0.w, q1.x,q1.y,q1.z,q1.w,
                     q2.x,q2.y,q2.z,q2.w, q3.x,q3.y,q3.z,q3.w };
    float rb[16] = { p0.x,p0.y,p0.z,p0.w, p1.x,p1.y,p1.z,p1.w,
                     p2.x,p2.y,p2.z,p2.w, p3.x,p3.y,p3.z,p3.w };

    // y[j] = log(Y[:,4+j] - Y[:,3+j] + 0.1), j = 0..10 (scan uses first 11 diffs)
    u64 y[11];
#pragma unroll
    for (int j = 0; j < 11; j++) {
        float d0 = __logf(ra[4 + j] - ra[3 + j] + 0.1f);
        float d1 = __logf(rb[4 + j] - rb[3 + j] + 0.1f);
        y[j] = pack2(d0, d1);
    }

    // ---- RNN: flow = tanh([flow, y_j] @ f1W^T + f1b), 11 steps ----
    // step 0: flow == 0, so acc = y0 * W[:,8] + b
    u64 flow[8];
#pragma unroll
    for (int i = 0; i < 8; i++)
        flow[i] = tanh2(ffma2(y[0], sW1[i * 9 + 8], sB1[i]));

#pragma unroll
    for (int j = 1; j < 11; j++) {
        u64 acc[8];
#pragma unroll
        for (int i = 0; i < 8; i++) {
            u64 a1 = sB1[i];
#pragma unroll
            for (int k = 0; k < 8; k++) a1 = ffma2(flow[k], sW1[i * 9 + k], a1);
            a1 = ffma2(y[j], sW1[i * 9 + 8], a1);
            acc[i] = a1;
        }
#pragma unroll
        for (int i = 0; i < 8; i++) flow[i] = tanh2(acc[i]);
    }

    // ---- f2 layer 0: tanh(flow @ W20^T + b20' + tau * sp(Wtau)^T) ----
    u64 taup;
    {
        float2 tv = *(const float2*)(tau + r0);
        taup = pack2(tv.x, tv.y);
    }
    u64 g[8];
#pragma unroll
    for (int i = 0; i < 8; i++) {
        u64 a1 = sB20[i];
        a1 = ffma2(taup, sTW[i], a1);
#pragma unroll
        for (int k = 0; k < 8; k++) a1 = ffma2(flow[k], sW20[i * 8 + k], a1);
        g[i] = tanh2(a1);
    }

    // ---- f2 layer 1: tanh(g @ sp(W21)^T + sp(b21)) ----
    u64 h[8];
#pragma unroll
    for (int i = 0; i < 8; i++) {
        u64 a1 = sB21[i];
#pragma unroll
        for (int k = 0; k < 8; k++) a1 = ffma2(g[k], sW21[i * 8 + k], a1);
        h[i] = tanh2(a1);
    }

    // ---- output: softplus(h @ sp(W22)^T + sp(b22)) ----
    u64 o = sB22;
#pragma unroll
    for (int k = 0; k < 8; k++) o = ffma2(h[k], sW22[k], o);

    float o0, o1; unpack2(o, o0, o1);
    float2 res;
    res.x = softplus_out(o0);
    res.y = softplus_out(o1);
    *(float2*)(out + r0) = res;
}

extern "C" void kernel_launch(void* const* d_in, const int* in_sizes, int n_in,
                              void* d_out, int out_size)
{
    const float* Y    = (const float*)d_in[0];
    const float* tau  = (const float*)d_in[1];
    const float* f1W  = (const float*)d_in[2];
    const float* f1b  = (const float*)d_in[3];
    const float* ftW  = (const float*)d_in[4];
    const float* ftb  = (const float*)d_in[5];
    const float* f20W = (const float*)d_in[6];
    const float* f20b = (const float*)d_in[7];
    const float* f21W = (const float*)d_in[8];
    const float* f21b = (const float*)d_in[9];
    const float* f22W = (const float*)d_in[10];
    const float* f22b = (const float*)d_in[11];
    float* out = (float*)d_out;

    int npairs = out_size / 2;  // 2M threads, 2 rows each
    int blocks = (npairs + NTHREADS - 1) / NTHREADS;
    hazard_kernel<<<blocks, NTHREADS>>>(Y, tau, f1W, f1b, ftW, ftb,
                                        f20W, f20b, f21W, f21b, f22W, f22b,
                                        out, npairs);
}